// round 16
// baseline (speedup 1.0000x reference)
#include <cuda_runtime.h>
#include <cuda_bf16.h>
#include <cstdint>

// ---------------- problem constants ----------------
constexpr int BB = 8;      // batch
constexpr int CC = 512;    // channels
constexpr int HH = 56, WW = 56;
constexpr int NT = 3136;   // H*W tokens
constexpr int MT = 588;    // 3*196 downsampled tokens
constexpr int NH = 8;      // heads
constexpr int HD = 64;     // head dim
constexpr int NP = 3200;   // NT padded to 128
constexpr int MP = 640;    // MT padded to 128
#define ATT_SCALE 0.125f

// ---------------- scratch (device globals; zero-initialized) ----------------
__device__ float g_lf[BB * MT * CC];

__device__ __nv_bfloat16 g_xh[(size_t)BB * NP * CC], g_xl[(size_t)BB * NP * CC];
__device__ __nv_bfloat16 g_wqh[CC * CC];                                   // single (2-term qproj)
__device__ __nv_bfloat16 g_wkh[2 * CC * CC], g_wkl[2 * CC * CC];           // hi for all, lo for V blocks
__device__ __nv_bfloat16 g_lh[(size_t)BB * MP * CC], g_ll[(size_t)BB * MP * CC];
__device__ __nv_bfloat16 g_qh[(size_t)BB * NP * CC];                       // Q single bf16
__device__ __nv_bfloat16 g_kh[(size_t)BB * NH * MP * HD];                  // K single bf16
__device__ __nv_bfloat16 g_vth[(size_t)BB * NH * HD * MP], g_vtl[(size_t)BB * NH * HD * MP];

// ---------------- PTX helpers ----------------
__device__ __forceinline__ uint32_t smem_u32_of(const void* p) {
    uint32_t a;
    asm("{ .reg .u64 t; cvta.to.shared.u64 t, %1; cvt.u32.u64 %0, t; }" : "=r"(a) : "l"(p));
    return a;
}
__device__ __forceinline__ void cpa16(uint32_t dst, const void* src) {
    asm volatile("cp.async.cg.shared.global [%0], [%1], 16;" :: "r"(dst), "l"(src));
}
__device__ __forceinline__ void ldm4(uint32_t addr, uint32_t& r0, uint32_t& r1,
                                     uint32_t& r2, uint32_t& r3) {
    asm volatile("ldmatrix.sync.aligned.m8n8.x4.shared.b16 {%0,%1,%2,%3}, [%4];"
                 : "=r"(r0), "=r"(r1), "=r"(r2), "=r"(r3) : "r"(addr));
}
__device__ __forceinline__ void mma16816(float* d, const uint32_t* a, const uint32_t* b) {
    asm volatile(
        "mma.sync.aligned.m16n8k16.row.col.f32.bf16.bf16.f32 "
        "{%0,%1,%2,%3}, {%4,%5,%6,%7}, {%8,%9}, {%0,%1,%2,%3};"
        : "+f"(d[0]), "+f"(d[1]), "+f"(d[2]), "+f"(d[3])
        : "r"(a[0]), "r"(a[1]), "r"(a[2]), "r"(a[3]), "r"(b[0]), "r"(b[1]));
}
__device__ __forceinline__ uint32_t pack_bf2(float lo, float hi) {
    __nv_bfloat16 a = __float2bfloat16(lo), b = __float2bfloat16(hi);
    return ((uint32_t)__bfloat16_as_ushort(b) << 16) | (uint32_t)__bfloat16_as_ushort(a);
}
__device__ __forceinline__ float b2f_lo(uint32_t p) {
    return __bfloat162float(__ushort_as_bfloat16((unsigned short)(p & 0xffff)));
}
__device__ __forceinline__ float b2f_hi(uint32_t p) {
    return __bfloat162float(__ushort_as_bfloat16((unsigned short)(p >> 16)));
}

// ================= GEMM engine A: 3-term, 4 tiles, 3-stage ring =========
constexpr int GSTAGE3 = 30720;
constexpr int GEMM3_SMEM = 3 * GSTAGE3;    // 92160

__device__ __forceinline__ void g3_load(const __nv_bfloat16* Ah, const __nv_bfloat16* Al,
                                        const __nv_bfloat16* Bh, const __nv_bfloat16* Bl,
                                        int lda, int ldb, uint32_t base, int koff, int t) {
    #pragma unroll
    for (int j = 0; j < 2; j++) {
        int g = j * 256 + t;
        int row = g >> 2, c16 = g & 3;
        cpa16(base +         row * 80 + c16 * 16, Ah + (size_t)row * lda + koff + c16 * 8);
        cpa16(base + 10240 + row * 80 + c16 * 16, Al + (size_t)row * lda + koff + c16 * 8);
    }
    {
        int row = t >> 2, c16 = t & 3;
        cpa16(base + 20480 + row * 80 + c16 * 16, Bh + (size_t)row * ldb + koff + c16 * 8);
        cpa16(base + 25600 + row * 80 + c16 * 16, Bl + (size_t)row * ldb + koff + c16 * 8);
    }
    asm volatile("cp.async.commit_group;");
}

__device__ __forceinline__ void gemm_main3(const __nv_bfloat16* Ah, const __nv_bfloat16* Al,
                                           const __nv_bfloat16* Bh, const __nv_bfloat16* Bl,
                                           int lda, int ldb, int nchunks,
                                           uint32_t su, float acc[2][4][4]) {
    const int t = threadIdx.x;
    const int lane = t & 31, wid = t >> 5;
    const int wm = wid & 3, wn = wid >> 2;

    g3_load(Ah, Al, Bh, Bl, lda, ldb, su, 0, t);
    if (nchunks > 1) g3_load(Ah, Al, Bh, Bl, lda, ldb, su + GSTAGE3, 32, t);
    int rb = 0;
    for (int i = 0; i < nchunks; i++) {
        if (i + 1 < nchunks) { asm volatile("cp.async.wait_group 1;" ::: "memory"); }
        else                 { asm volatile("cp.async.wait_group 0;" ::: "memory"); }
        __syncthreads();
        if (i + 2 < nchunks) {
            int wb = rb + 2; if (wb >= 3) wb -= 3;
            g3_load(Ah, Al, Bh, Bl, lda, ldb, su + wb * GSTAGE3, (i + 2) * 32, t);
        }
        const uint32_t ab = su + rb * GSTAGE3;
        #pragma unroll
        for (int k16 = 0; k16 < 2; k16++) {
            uint32_t afh[2][4], afl[2][4];
            uint32_t a_addr = ab + (wm * 32 + (lane & 15)) * 80 + k16 * 32 + (lane >> 4) * 16;
            ldm4(a_addr,                 afh[0][0], afh[0][1], afh[0][2], afh[0][3]);
            ldm4(a_addr + 16 * 80,       afh[1][0], afh[1][1], afh[1][2], afh[1][3]);
            ldm4(a_addr + 10240,         afl[0][0], afl[0][1], afl[0][2], afl[0][3]);
            ldm4(a_addr + 10240 + 1280,  afl[1][0], afl[1][1], afl[1][2], afl[1][3]);
            uint32_t bfh[4][2], bfl[4][2];
            #pragma unroll
            for (int p = 0; p < 2; p++) {
                uint32_t b_addr = ab + 20480 + (wn * 32 + p * 16 + (lane & 15)) * 80
                                + k16 * 32 + ((lane >> 4) & 1) * 16;
                uint32_t r0, r1, r2, r3;
                ldm4(b_addr, r0, r1, r2, r3);
                bfh[2 * p][0] = r0; bfh[2 * p + 1][0] = r1;
                bfh[2 * p][1] = r2; bfh[2 * p + 1][1] = r3;
                ldm4(b_addr + 5120, r0, r1, r2, r3);
                bfl[2 * p][0] = r0; bfl[2 * p + 1][0] = r1;
                bfl[2 * p][1] = r2; bfl[2 * p + 1][1] = r3;
            }
            #pragma unroll
            for (int mi = 0; mi < 2; mi++)
                #pragma unroll
                for (int ni = 0; ni < 4; ni++) {
                    mma16816(acc[mi][ni], afh[mi], bfh[ni]);
                    mma16816(acc[mi][ni], afh[mi], bfl[ni]);
                    mma16816(acc[mi][ni], afl[mi], bfh[ni]);
                }
        }
        if (++rb == 3) rb = 0;
    }
}

// ================= GEMM engine B: 2-term, 3 tiles, 3-stage ring =========
constexpr int GSTAGE2 = 25600;
constexpr int GEMM2_SMEM = 3 * GSTAGE2;    // 76800

__device__ __forceinline__ void g2t_load(const __nv_bfloat16* Ah, const __nv_bfloat16* Al,
                                         const __nv_bfloat16* Bh,
                                         int lda, int ldb, uint32_t base, int koff, int t) {
    #pragma unroll
    for (int j = 0; j < 2; j++) {
        int g = j * 256 + t;
        int row = g >> 2, c16 = g & 3;
        cpa16(base +         row * 80 + c16 * 16, Ah + (size_t)row * lda + koff + c16 * 8);
        cpa16(base + 10240 + row * 80 + c16 * 16, Al + (size_t)row * lda + koff + c16 * 8);
    }
    {
        int row = t >> 2, c16 = t & 3;
        cpa16(base + 20480 + row * 80 + c16 * 16, Bh + (size_t)row * ldb + koff + c16 * 8);
    }
    asm volatile("cp.async.commit_group;");
}

__device__ __forceinline__ void gemm_main2t(const __nv_bfloat16* Ah, const __nv_bfloat16* Al,
                                            const __nv_bfloat16* Bh,
                                            int lda, int ldb, int nchunks,
                                            uint32_t su, float acc[2][4][4]) {
    const int t = threadIdx.x;
    const int lane = t & 31, wid = t >> 5;
    const int wm = wid & 3, wn = wid >> 2;

    g2t_load(Ah, Al, Bh, lda, ldb, su, 0, t);
    if (nchunks > 1) g2t_load(Ah, Al, Bh, lda, ldb, su + GSTAGE2, 32, t);
    int rb = 0;
    for (int i = 0; i < nchunks; i++) {
        if (i + 1 < nchunks) { asm volatile("cp.async.wait_group 1;" ::: "memory"); }
        else                 { asm volatile("cp.async.wait_group 0;" ::: "memory"); }
        __syncthreads();
        if (i + 2 < nchunks) {
            int wb = rb + 2; if (wb >= 3) wb -= 3;
            g2t_load(Ah, Al, Bh, lda, ldb, su + wb * GSTAGE2, (i + 2) * 32, t);
        }
        const uint32_t ab = su + rb * GSTAGE2;
        #pragma unroll
        for (int k16 = 0; k16 < 2; k16++) {
            uint32_t afh[2][4], afl[2][4];
            uint32_t a_addr = ab + (wm * 32 + (lane & 15)) * 80 + k16 * 32 + (lane >> 4) * 16;
            ldm4(a_addr,                 afh[0][0], afh[0][1], afh[0][2], afh[0][3]);
            ldm4(a_addr + 16 * 80,       afh[1][0], afh[1][1], afh[1][2], afh[1][3]);
            ldm4(a_addr + 10240,         afl[0][0], afl[0][1], afl[0][2], afl[0][3]);
            ldm4(a_addr + 10240 + 1280,  afl[1][0], afl[1][1], afl[1][2], afl[1][3]);
            uint32_t bfh[4][2];
            #pragma unroll
            for (int p = 0; p < 2; p++) {
                uint32_t b_addr = ab + 20480 + (wn * 32 + p * 16 + (lane & 15)) * 80
                                + k16 * 32 + ((lane >> 4) & 1) * 16;
                uint32_t r0, r1, r2, r3;
                ldm4(b_addr, r0, r1, r2, r3);
                bfh[2 * p][0] = r0; bfh[2 * p + 1][0] = r1;
                bfh[2 * p][1] = r2; bfh[2 * p + 1][1] = r3;
            }
            #pragma unroll
            for (int mi = 0; mi < 2; mi++)
                #pragma unroll
                for (int ni = 0; ni < 4; ni++) {
                    mma16816(acc[mi][ni], afh[mi], bfh[ni]);
                    mma16816(acc[mi][ni], afl[mi], bfh[ni]);
                }
        }
        if (++rb == 3) rb = 0;
    }
}

#define EPILOGUE_ITER(body)                                                    \
    {                                                                          \
        const int lane = threadIdx.x & 31, wid = threadIdx.x >> 5;             \
        const int wm = wid & 3, wn = wid >> 2;                                 \
        _Pragma("unroll")                                                      \
        for (int mi = 0; mi < 2; mi++)                                         \
            _Pragma("unroll")                                                  \
            for (int ni = 0; ni < 4; ni++)                                     \
                _Pragma("unroll")                                              \
                for (int e = 0; e < 4; e++) {                                  \
                    int row = wm * 32 + mi * 16 + (lane >> 2) + ((e >> 1) * 8);\
                    int col = wn * 32 + ni * 8 + (lane & 3) * 2 + (e & 1);     \
                    float v = acc[mi][ni][e];                                  \
                    body                                                       \
                }                                                              \
    }

// ================= projection kernels =================
__global__ __launch_bounds__(256, 2) void k_qproj_t(const float* __restrict__ bq, int b0) {
    extern __shared__ __align__(128) uint8_t smem[];
    uint32_t su = smem_u32_of(smem);
    const int b = b0 + blockIdx.z, m0 = blockIdx.x * 128, n0 = blockIdx.y * 64;
    float acc[2][4][4] = {};
    gemm_main2t(g_xh + ((size_t)b * NP + m0) * CC, g_xl + ((size_t)b * NP + m0) * CC,
                g_wqh + (size_t)n0 * CC, CC, CC, 16, su, acc);
    EPILOGUE_ITER({
        v += bq[n0 + col];
        g_qh[((size_t)b * NP + m0 + row) * CC + n0 + col] = __float2bfloat16(v);
    })
}

// kvproj: K blocks (n0 < 512) use 2-term (K rounded to bf16 anyway); V blocks 3-term
__global__ __launch_bounds__(256, 2) void k_kvproj_t(const float* __restrict__ bkv) {
    extern __shared__ __align__(128) uint8_t smem[];
    uint32_t su = smem_u32_of(smem);
    const int b = blockIdx.z, m0 = blockIdx.x * 128, n0 = blockIdx.y * 64;
    float acc[2][4][4] = {};
    if (n0 < 512) {
        gemm_main2t(g_lh + ((size_t)b * MP + m0) * CC, g_ll + ((size_t)b * MP + m0) * CC,
                    g_wkh + (size_t)n0 * CC, CC, CC, 16, su, acc);
        EPILOGUE_ITER({
            int o = n0 + col;
            int m = m0 + row;
            v += bkv[o];
            g_kh[(((size_t)b * NH + (o >> 6)) * MP + m) * HD + (o & 63)] = __float2bfloat16(v);
        })
    } else {
        gemm_main3(g_lh + ((size_t)b * MP + m0) * CC, g_ll + ((size_t)b * MP + m0) * CC,
                   g_wkh + (size_t)n0 * CC, g_wkl + (size_t)n0 * CC,
                   CC, CC, 16, su, acc);
        EPILOGUE_ITER({
            int o2 = n0 + col - 512;
            int m = m0 + row;
            v += bkv[n0 + col];
            size_t idx = (((size_t)b * NH + (o2 >> 6)) * HD + (o2 & 63)) * MP + m;
            __nv_bfloat16 h = __float2bfloat16(v);
            g_vth[idx] = h;
            g_vtl[idx] = __float2bfloat16(v - __bfloat162float(h));
        })
    }
}

// ================= fused flash attention =================
// smem: Qh[128][144] @0 (18432); chunk buf @18432 + buf*27648:
//   Kh 64x144 (9216), Vh +9216, Vl +18432.  total 73728.
constexpr int FPITCH  = 144;
constexpr int Q_BYTES = 128 * FPITCH;          // 18432
constexpr int T_BYTES = 64 * FPITCH;           // 9216
constexpr int CH_OFF  = Q_BYTES;               // 18432
constexpr int CH_SIZE = 3 * T_BYTES;           // 27648
constexpr int FLASH_SMEM = CH_OFF + 2 * CH_SIZE;   // 73728

__global__ __launch_bounds__(256, 2) void k_flash(float* __restrict__ out, int bh0) {
    extern __shared__ __align__(128) uint8_t fsm[];
    uint32_t su = smem_u32_of(fsm);
    const int bh = bh0 + blockIdx.y, b = bh >> 3, h = bh & 7;
    const int n0 = blockIdx.x * 128;
    const int t = threadIdx.x, lane = t & 31, w = t >> 5;

    const __nv_bfloat16* qhp = g_qh + ((size_t)b * NP + n0) * CC + h * HD;
    const __nv_bfloat16* khp = g_kh + (size_t)bh * MP * HD;
    const __nv_bfloat16* vhp = g_vth + (size_t)bh * HD * MP;
    const __nv_bfloat16* vlp = g_vtl + (size_t)bh * HD * MP;

    #pragma unroll
    for (int j = 0; j < 4; j++) {
        int g = j * 256 + t, row = g >> 3, c16 = g & 7;
        cpa16(su + row * FPITCH + c16 * 16, qhp + (size_t)row * CC + c16 * 8);
    }
    asm volatile("cp.async.commit_group;");

    auto load_chunk = [&](int ci, int buf) {
        uint32_t base = su + CH_OFF + buf * CH_SIZE;
        #pragma unroll
        for (int j = 0; j < 2; j++) {
            int g = j * 256 + t, row = g >> 3, c16 = g & 7;
            cpa16(base +               row * FPITCH + c16 * 16,
                  khp + (size_t)(ci * 64 + row) * HD + c16 * 8);
            cpa16(base + T_BYTES +     row * FPITCH + c16 * 16,
                  vhp + (size_t)row * MP + ci * 64 + c16 * 8);
            cpa16(base + 2 * T_BYTES + row * FPITCH + c16 * 16,
                  vlp + (size_t)row * MP + ci * 64 + c16 * 8);
        }
        asm volatile("cp.async.commit_group;");
    };
    load_chunk(0, 0);

    float l0 = 0.f, l1 = 0.f;
    float oa[8][4] = {};

    const uint32_t q_frag_base = su + (w * 16 + (lane & 15)) * FPITCH + (lane >> 4) * 16;
    const uint32_t kb_row = (lane & 15) * FPITCH + ((lane >> 4) & 1) * 16;

    for (int ci = 0; ci < 10; ci++) {
        const int buf = ci & 1;
        const uint32_t kb = su + CH_OFF + buf * CH_SIZE;

        asm volatile("cp.async.wait_group 0;" ::: "memory");
        __syncthreads();
        if (ci + 1 < 10) load_chunk(ci + 1, buf ^ 1);

        // ---- S = Qh * Kh  (1-term; Q and K both bf16-rounded upstream) ----
        float sa[8][4] = {};
        #pragma unroll
        for (int g = 0; g < 4; g++) {
            uint32_t qfh[4];
            ldm4(q_frag_base + g * 32, qfh[0], qfh[1], qfh[2], qfh[3]);
            #pragma unroll
            for (int half = 0; half < 2; half++) {
                uint32_t bkh[4][2];
                #pragma unroll
                for (int p = 0; p < 2; p++) {
                    uint32_t addr = kb + (half * 32 + p * 16) * FPITCH + kb_row + g * 32;
                    uint32_t r0, r1, r2, r3;
                    ldm4(addr, r0, r1, r2, r3);
                    bkh[2 * p][0] = r0; bkh[2 * p + 1][0] = r1;
                    bkh[2 * p][1] = r2; bkh[2 * p + 1][1] = r3;
                }
                #pragma unroll
                for (int nb2 = 0; nb2 < 4; nb2++)
                    mma16816(sa[half * 4 + nb2], qfh, bkh[nb2]);
            }
        }

        // ---- fixed-shift softmax ----
        float ps0 = 0.f, ps1 = 0.f;
        if (ci == 9) {
            #pragma unroll
            for (int nb = 0; nb < 8; nb++)
                #pragma unroll
                for (int e = 0; e < 4; e++) {
                    int j = 576 + nb * 8 + (lane & 3) * 2 + (e & 1);
                    float ev = (j < MT) ? __expf(sa[nb][e] * ATT_SCALE) : 0.f;
                    sa[nb][e] = ev;
                    if (e < 2) ps0 += ev; else ps1 += ev;
                }
        } else {
            #pragma unroll
            for (int nb = 0; nb < 8; nb++)
                #pragma unroll
                for (int e = 0; e < 4; e++) {
                    float ev = __expf(sa[nb][e] * ATT_SCALE);
                    sa[nb][e] = ev;
                    if (e < 2) ps0 += ev; else ps1 += ev;
                }
        }
        ps0 += __shfl_xor_sync(0xffffffffu, ps0, 1);
        ps0 += __shfl_xor_sync(0xffffffffu, ps0, 2);
        ps1 += __shfl_xor_sync(0xffffffffu, ps1, 1);
        ps1 += __shfl_xor_sync(0xffffffffu, ps1, 2);
        l0 += ps0;
        l1 += ps1;

        // ---- PV: O += Ph*Vh + Ph*Vl + Pl*Vh  (3-term; direct output path) ----
        #pragma unroll
        for (int g = 0; g < 4; g++) {
            uint32_t aph[4], apl[4];
            #pragma unroll
            for (int q = 0; q < 2; q++) {
                int nb = 2 * g + q;
                float p0 = sa[nb][0], p1 = sa[nb][1], p2 = sa[nb][2], p3 = sa[nb][3];
                uint32_t hi01 = pack_bf2(p0, p1);
                uint32_t hi23 = pack_bf2(p2, p3);
                aph[2 * q]     = hi01;
                aph[2 * q + 1] = hi23;
                apl[2 * q]     = pack_bf2(p0 - b2f_lo(hi01), p1 - b2f_hi(hi01));
                apl[2 * q + 1] = pack_bf2(p2 - b2f_lo(hi23), p3 - b2f_hi(hi23));
            }
            #pragma unroll
            for (int half = 0; half < 2; half++) {
                uint32_t bvh[4][2], bvl[4][2];
                #pragma unroll
                for (int p = 0; p < 2; p++) {
                    uint32_t addr = kb + T_BYTES + (half * 32 + p * 16) * FPITCH
                                  + kb_row + g * 32;
                    uint32_t r0, r1, r2, r3;
                    ldm4(addr, r0, r1, r2, r3);
                    bvh[2 * p][0] = r0; bvh[2 * p + 1][0] = r1;
                    bvh[2 * p][1] = r2; bvh[2 * p + 1][1] = r3;
                    ldm4(addr + T_BYTES, r0, r1, r2, r3);
                    bvl[2 * p][0] = r0; bvl[2 * p + 1][0] = r1;
                    bvl[2 * p][1] = r2; bvl[2 * p + 1][1] = r3;
                }
                #pragma unroll
                for (int nd2 = 0; nd2 < 4; nd2++) {
                    int nd = half * 4 + nd2;
                    mma16816(oa[nd], aph, bvh[nd2]);
                    mma16816(oa[nd], aph, bvl[nd2]);
                    mma16816(oa[nd], apl, bvh[nd2]);
                }
            }
        }
    }

    const float inv0 = 1.f / l0, inv1 = 1.f / l1;
    const int r0 = w * 16 + (lane >> 2);
    const int nq0 = n0 + r0, nq1 = nq0 + 8;
    #pragma unroll
    for (int nd = 0; nd < 8; nd++) {
        int d = h * HD + nd * 8 + (lane & 3) * 2;
        if (nq0 < NT) {
            float2 v = make_float2(oa[nd][0] * inv0, oa[nd][1] * inv0);
            *(float2*)(out + ((size_t)b * NT + nq0) * CC + d) = v;
        }
        if (nq1 < NT) {
            float2 v = make_float2(oa[nd][2] * inv1, oa[nd][3] * inv1);
            *(float2*)(out + ((size_t)b * NT + nq1) * CC + d) = v;
        }
    }
}

// ================= support kernels =================
__global__ __launch_bounds__(256) void k_tsplit(const float* __restrict__ x) {
    __shared__ float tile[32][33];
    const int b = blockIdx.z, n0 = blockIdx.x * 32, c0 = blockIdx.y * 32;
    const int tx = threadIdx.x & 31, ty = threadIdx.x >> 5;
    const float* xp = x + ((size_t)b * CC + c0) * NT + n0;
    #pragma unroll
    for (int i = 0; i < 4; i++)
        tile[ty + 8 * i][tx] = xp[(size_t)(ty + 8 * i) * NT + tx];
    __syncthreads();
    #pragma unroll
    for (int i = 0; i < 4; i++) {
        int r = ty + 8 * i;
        float v = tile[tx][r];
        size_t o = ((size_t)b * NP + n0 + r) * CC + c0 + tx;
        __nv_bfloat16 h = __float2bfloat16(v);
        g_xh[o] = h;
        g_xl[o] = __float2bfloat16(v - __bfloat162float(h));
    }
}

__global__ void k_splitw(const float* __restrict__ Wq, const float* __restrict__ Wkv) {
    int i = blockIdx.x * 256 + threadIdx.x;
    if (i < CC * CC) {
        g_wqh[i] = __float2bfloat16(Wq[i]);
    }
    if (i < 2 * CC * CC) {
        float v = Wkv[i];
        __nv_bfloat16 h = __float2bfloat16(v);
        g_wkh[i] = h; g_wkl[i] = __float2bfloat16(v - __bfloat162float(h));
    }
}

// fused branches 1, 2, 3: one block per (b, c); pooled plane staged in SMEM
__global__ __launch_bounds__(224) void k_branch(const float* __restrict__ x,
        const float* __restrict__ w1a, const float* __restrict__ b1a,
        const float* __restrict__ w1b, const float* __restrict__ b1b,
        const float* __restrict__ w2, const float* __restrict__ b2,
        const float* __restrict__ w3, const float* __restrict__ b3) {
    __shared__ float pool_s[196];
    const int bc = blockIdx.x;
    const int b = bc / CC, c = bc % CC;
    const int t = threadIdx.x;

    if (t < 196) {
        int w4 = t % 14, h4 = t / 14;
        const float* xp = x + (((size_t)bc * HH) + 4 * h4) * WW + 4 * w4;
        float wa[4], wb_[4], wc[16];
        #pragma unroll
        for (int r = 0; r < 4; r++) { wa[r] = w1a[c * 4 + r]; wb_[r] = w1b[c * 4 + r]; }
        #pragma unroll
        for (int r = 0; r < 16; r++) wc[r] = w2[c * 16 + r];
        float ba = b1a[c];
        float l1 = b1b[c], l2 = b2[c], pool = 0.f;
        #pragma unroll
        for (int i = 0; i < 4; i++) {
            float4 xv = *(const float4*)(xp + (size_t)i * WW);
            float tmid = ba + xv.x * wa[0] + xv.y * wa[1] + xv.z * wa[2] + xv.w * wa[3];
            l1 += fmaxf(tmid, 0.f) * wb_[i];
            l2 += xv.x * wc[4 * i] + xv.y * wc[4 * i + 1] + xv.z * wc[4 * i + 2] + xv.w * wc[4 * i + 3];
            pool += xv.x + xv.y + xv.z + xv.w;
        }
        g_lf[((size_t)b * MT + t) * CC + c] = fmaxf(l1, 0.f);
        g_lf[((size_t)b * MT + 196 + t) * CC + c] = fmaxf(l2, 0.f);
        pool_s[t] = pool * (1.f / 16.f);
    }
    __syncthreads();
    if (t < 196) {
        int w4 = t % 14, h4 = t / 14;
        float s = b3[c];
        #pragma unroll
        for (int i = 0; i < 3; i++) {
            int hh = h4 - 1 + i;
            if (hh < 0 || hh >= 14) continue;
            #pragma unroll
            for (int j = 0; j < 3; j++) {
                int ww = w4 - 1 + j;
                if (ww < 0 || ww >= 14) continue;
                s += pool_s[hh * 14 + ww] * w3[c * 9 + i * 3 + j];
            }
        }
        g_lf[((size_t)b * MT + 392 + t) * CC + c] = fmaxf(s, 0.f);
    }
}

__global__ __launch_bounds__(128) void k_ln(const float* __restrict__ gamma,
                                            const float* __restrict__ beta) {
    const int row = blockIdx.x;
    const int b = row / MT, m = row - b * MT;
    const float* p = g_lf + (size_t)row * CC;
    const int t = threadIdx.x;
    float4 v = *(const float4*)(p + t * 4);
    float s = v.x + v.y + v.z + v.w;
    float ss = v.x * v.x + v.y * v.y + v.z * v.z + v.w * v.w;
    #pragma unroll
    for (int o = 16; o >= 1; o >>= 1) {
        s  += __shfl_xor_sync(0xffffffffu, s, o);
        ss += __shfl_xor_sync(0xffffffffu, ss, o);
    }
    __shared__ float sh[8];
    int w = t >> 5;
    if ((t & 31) == 0) { sh[w * 2] = s; sh[w * 2 + 1] = ss; }
    __syncthreads();
    s  = sh[0] + sh[2] + sh[4] + sh[6];
    ss = sh[1] + sh[3] + sh[5] + sh[7];
    float mu = s * (1.f / CC);
    float var = ss * (1.f / CC) - mu * mu;
    float r = rsqrtf(var + 1e-5f);
    float4 g = *(const float4*)(gamma + t * 4);
    float4 be = *(const float4*)(beta + t * 4);
    float o0 = (v.x - mu) * r * g.x + be.x;
    float o1 = (v.y - mu) * r * g.y + be.y;
    float o2 = (v.z - mu) * r * g.z + be.z;
    float o3 = (v.w - mu) * r * g.w + be.w;
    size_t base = ((size_t)b * MP + m) * CC + t * 4;
    __nv_bfloat16 h0 = __float2bfloat16(o0), h1 = __float2bfloat16(o1);
    __nv_bfloat16 h2 = __float2bfloat16(o2), h3 = __float2bfloat16(o3);
    g_lh[base + 0] = h0; g_ll[base + 0] = __float2bfloat16(o0 - __bfloat162float(h0));
    g_lh[base + 1] = h1; g_ll[base + 1] = __float2bfloat16(o1 - __bfloat162float(h1));
    g_lh[base + 2] = h2; g_ll[base + 2] = __float2bfloat16(o2 - __bfloat162float(h2));
    g_lh[base + 3] = h3; g_ll[base + 3] = __float2bfloat16(o3 - __bfloat162float(h3));
}

// ---------------- launch: pipelined schedule with tail-filling streams ----------------
extern "C" void kernel_launch(void* const* d_in, const int* in_sizes, int n_in,
                              void* d_out, int out_size) {
    const float* x     = (const float*)d_in[0];
    const float* Wq    = (const float*)d_in[1];
    const float* bq    = (const float*)d_in[2];
    const float* Wkv   = (const float*)d_in[3];
    const float* bkv   = (const float*)d_in[4];
    const float* w1a   = (const float*)d_in[5];
    const float* b1a   = (const float*)d_in[6];
    const float* w1b   = (const float*)d_in[7];
    const float* b1b   = (const float*)d_in[8];
    const float* w2    = (const float*)d_in[9];
    const float* b2    = (const float*)d_in[10];
    const float* w3    = (const float*)d_in[11];
    const float* b3    = (const float*)d_in[12];
    const float* gamma = (const float*)d_in[13];
    const float* beta  = (const float*)d_in[14];
    float* out = (float*)d_out;

    // one-time resource init (identical captured graph every call)
    static cudaStream_t s2 = nullptr, f0 = nullptr, f1 = nullptr;
    static cudaEvent_t e_fork = nullptr, e_kv = nullptr, e_d0 = nullptr, e_d1 = nullptr;
    static cudaEvent_t e_q[2] = {nullptr, nullptr};
    if (s2 == nullptr) {
        cudaStreamCreateWithFlags(&s2, cudaStreamNonBlocking);
        cudaStreamCreateWithFlags(&f0, cudaStreamNonBlocking);
        cudaStreamCreateWithFlags(&f1, cudaStreamNonBlocking);
        cudaEventCreateWithFlags(&e_fork, cudaEventDisableTiming);
        cudaEventCreateWithFlags(&e_kv,   cudaEventDisableTiming);
        cudaEventCreateWithFlags(&e_d0,   cudaEventDisableTiming);
        cudaEventCreateWithFlags(&e_d1,   cudaEventDisableTiming);
        for (int i = 0; i < 2; i++) cudaEventCreateWithFlags(&e_q[i], cudaEventDisableTiming);
        cudaFuncSetAttribute(k_flash,    cudaFuncAttributeMaxDynamicSharedMemorySize, FLASH_SMEM);
        cudaFuncSetAttribute(k_qproj_t,  cudaFuncAttributeMaxDynamicSharedMemorySize, GEMM2_SMEM);
        cudaFuncSetAttribute(k_kvproj_t, cudaFuncAttributeMaxDynamicSharedMemorySize, GEMM3_SMEM);
    }

    // main stream: weight split (needed by both chains), then fork
    k_splitw<<<(2 * CC * CC + 255) / 256, 256>>>(Wq, Wkv);
    cudaEventRecord(e_fork, 0);
    cudaStreamWaitEvent(s2, e_fork, 0);

    // side chain (s2): branches -> LN -> KV projection -> e_kv
    k_branch<<<BB * CC, 224, 0, s2>>>(x, w1a, b1a, w1b, b1b, w2, b2, w3, b3);
    k_ln<<<BB * MT, 128, 0, s2>>>(gamma, beta);
    k_kvproj_t<<<dim3(MP / 128, 2 * CC / 64, BB), 256, GEMM3_SMEM, s2>>>(bkv);
    cudaEventRecord(e_kv, s2);

    // main chain: x transpose/split, then 2 qproj halves (4 batches each)
    k_tsplit<<<dim3(NT / 32, CC / 32, BB), 256>>>(x);
    for (int half = 0; half < 2; half++) {
        k_qproj_t<<<dim3(NP / 128, CC / 64, 4), 256, GEMM2_SMEM>>>(bq, 4 * half);
        cudaEventRecord(e_q[half], 0);
    }

    // flash: 4 slices (2 batches each) alternating across two streams
    cudaStreamWaitEvent(f0, e_kv, 0);
    cudaStreamWaitEvent(f1, e_kv, 0);
    for (int sIdx = 0; sIdx < 4; sIdx++) {
        cudaStream_t fs = (sIdx & 1) ? f1 : f0;
        cudaStreamWaitEvent(fs, e_q[sIdx >> 1], 0);
        k_flash<<<dim3(NP / 128, 2 * NH), 256, FLASH_SMEM, fs>>>(out, 2 * sIdx * NH);
    }
    cudaEventRecord(e_d0, f0);
    cudaEventRecord(e_d1, f1);

    // join everything back into the capture stream
    cudaStreamWaitEvent(0, e_d0, 0);
    cudaStreamWaitEvent(0, e_d1, 0);
}

// round 17
// speedup vs baseline: 1.5120x; 1.5120x over previous
#include <cuda_runtime.h>
#include <cuda_bf16.h>
#include <cstdint>

// ---------------- problem constants ----------------
constexpr int BB = 8;      // batch
constexpr int CC = 512;    // channels
constexpr int HH = 56, WW = 56;
constexpr int NT = 3136;   // H*W tokens
constexpr int MT = 588;    // 3*196 downsampled tokens
constexpr int NH = 8;      // heads
constexpr int HD = 64;     // head dim
constexpr int NP = 3200;   // NT padded to 128
constexpr int MP = 640;    // MT padded to 128
#define ATT_SCALE 0.125f

// ---------------- scratch (device globals; zero-initialized) ----------------
__device__ float g_lf[BB * MT * CC];

__device__ __nv_bfloat16 g_xh[(size_t)BB * NP * CC], g_xl[(size_t)BB * NP * CC];
__device__ __nv_bfloat16 g_wqh[CC * CC];                                   // single (2-term qproj)
__device__ __nv_bfloat16 g_wkh[2 * CC * CC], g_wkl[2 * CC * CC];           // hi all; lo used by V
__device__ __nv_bfloat16 g_lh[(size_t)BB * MP * CC], g_ll[(size_t)BB * MP * CC];
__device__ __nv_bfloat16 g_qh[(size_t)BB * NP * CC];                       // Q single bf16
__device__ __nv_bfloat16 g_kh[(size_t)BB * NH * MP * HD];                  // K single bf16
__device__ __nv_bfloat16 g_vth[(size_t)BB * NH * HD * MP], g_vtl[(size_t)BB * NH * HD * MP];

// ---------------- PTX helpers ----------------
__device__ __forceinline__ uint32_t smem_u32_of(const void* p) {
    uint32_t a;
    asm("{ .reg .u64 t; cvta.to.shared.u64 t, %1; cvt.u32.u64 %0, t; }" : "=r"(a) : "l"(p));
    return a;
}
__device__ __forceinline__ void cpa16(uint32_t dst, const void* src) {
    asm volatile("cp.async.cg.shared.global [%0], [%1], 16;" :: "r"(dst), "l"(src));
}
__device__ __forceinline__ void ldm4(uint32_t addr, uint32_t& r0, uint32_t& r1,
                                     uint32_t& r2, uint32_t& r3) {
    asm volatile("ldmatrix.sync.aligned.m8n8.x4.shared.b16 {%0,%1,%2,%3}, [%4];"
                 : "=r"(r0), "=r"(r1), "=r"(r2), "=r"(r3) : "r"(addr));
}
__device__ __forceinline__ void mma16816(float* d, const uint32_t* a, const uint32_t* b) {
    asm volatile(
        "mma.sync.aligned.m16n8k16.row.col.f32.bf16.bf16.f32 "
        "{%0,%1,%2,%3}, {%4,%5,%6,%7}, {%8,%9}, {%0,%1,%2,%3};"
        : "+f"(d[0]), "+f"(d[1]), "+f"(d[2]), "+f"(d[3])
        : "r"(a[0]), "r"(a[1]), "r"(a[2]), "r"(a[3]), "r"(b[0]), "r"(b[1]));
}
__device__ __forceinline__ uint32_t pack_bf2(float lo, float hi) {
    __nv_bfloat16 a = __float2bfloat16(lo), b = __float2bfloat16(hi);
    return ((uint32_t)__bfloat16_as_ushort(b) << 16) | (uint32_t)__bfloat16_as_ushort(a);
}
__device__ __forceinline__ float b2f_lo(uint32_t p) {
    return __bfloat162float(__ushort_as_bfloat16((unsigned short)(p & 0xffff)));
}
__device__ __forceinline__ float b2f_hi(uint32_t p) {
    return __bfloat162float(__ushort_as_bfloat16((unsigned short)(p >> 16)));
}

// ================= GEMM engine A: 3-term, 4 tiles, 3-stage ring =========
constexpr int GSTAGE3 = 30720;
constexpr int GEMM3_SMEM = 3 * GSTAGE3;    // 92160

__device__ __forceinline__ void g3_load(const __nv_bfloat16* Ah, const __nv_bfloat16* Al,
                                        const __nv_bfloat16* Bh, const __nv_bfloat16* Bl,
                                        int lda, int ldb, uint32_t base, int koff, int t) {
    #pragma unroll
    for (int j = 0; j < 2; j++) {
        int g = j * 256 + t;
        int row = g >> 2, c16 = g & 3;
        cpa16(base +         row * 80 + c16 * 16, Ah + (size_t)row * lda + koff + c16 * 8);
        cpa16(base + 10240 + row * 80 + c16 * 16, Al + (size_t)row * lda + koff + c16 * 8);
    }
    {
        int row = t >> 2, c16 = t & 3;
        cpa16(base + 20480 + row * 80 + c16 * 16, Bh + (size_t)row * ldb + koff + c16 * 8);
        cpa16(base + 25600 + row * 80 + c16 * 16, Bl + (size_t)row * ldb + koff + c16 * 8);
    }
    asm volatile("cp.async.commit_group;");
}

__device__ __forceinline__ void gemm_main3(const __nv_bfloat16* Ah, const __nv_bfloat16* Al,
                                           const __nv_bfloat16* Bh, const __nv_bfloat16* Bl,
                                           int lda, int ldb, int nchunks,
                                           uint32_t su, float acc[2][4][4]) {
    const int t = threadIdx.x;
    const int lane = t & 31, wid = t >> 5;
    const int wm = wid & 3, wn = wid >> 2;

    g3_load(Ah, Al, Bh, Bl, lda, ldb, su, 0, t);
    if (nchunks > 1) g3_load(Ah, Al, Bh, Bl, lda, ldb, su + GSTAGE3, 32, t);
    int rb = 0;
    for (int i = 0; i < nchunks; i++) {
        if (i + 1 < nchunks) { asm volatile("cp.async.wait_group 1;" ::: "memory"); }
        else                 { asm volatile("cp.async.wait_group 0;" ::: "memory"); }
        __syncthreads();
        if (i + 2 < nchunks) {
            int wb = rb + 2; if (wb >= 3) wb -= 3;
            g3_load(Ah, Al, Bh, Bl, lda, ldb, su + wb * GSTAGE3, (i + 2) * 32, t);
        }
        const uint32_t ab = su + rb * GSTAGE3;
        #pragma unroll
        for (int k16 = 0; k16 < 2; k16++) {
            uint32_t afh[2][4], afl[2][4];
            uint32_t a_addr = ab + (wm * 32 + (lane & 15)) * 80 + k16 * 32 + (lane >> 4) * 16;
            ldm4(a_addr,                 afh[0][0], afh[0][1], afh[0][2], afh[0][3]);
            ldm4(a_addr + 16 * 80,       afh[1][0], afh[1][1], afh[1][2], afh[1][3]);
            ldm4(a_addr + 10240,         afl[0][0], afl[0][1], afl[0][2], afl[0][3]);
            ldm4(a_addr + 10240 + 1280,  afl[1][0], afl[1][1], afl[1][2], afl[1][3]);
            uint32_t bfh[4][2], bfl[4][2];
            #pragma unroll
            for (int p = 0; p < 2; p++) {
                uint32_t b_addr = ab + 20480 + (wn * 32 + p * 16 + (lane & 15)) * 80
                                + k16 * 32 + ((lane >> 4) & 1) * 16;
                uint32_t r0, r1, r2, r3;
                ldm4(b_addr, r0, r1, r2, r3);
                bfh[2 * p][0] = r0; bfh[2 * p + 1][0] = r1;
                bfh[2 * p][1] = r2; bfh[2 * p + 1][1] = r3;
                ldm4(b_addr + 5120, r0, r1, r2, r3);
                bfl[2 * p][0] = r0; bfl[2 * p + 1][0] = r1;
                bfl[2 * p][1] = r2; bfl[2 * p + 1][1] = r3;
            }
            #pragma unroll
            for (int mi = 0; mi < 2; mi++)
                #pragma unroll
                for (int ni = 0; ni < 4; ni++) {
                    mma16816(acc[mi][ni], afh[mi], bfh[ni]);
                    mma16816(acc[mi][ni], afh[mi], bfl[ni]);
                    mma16816(acc[mi][ni], afl[mi], bfh[ni]);
                }
        }
        if (++rb == 3) rb = 0;
    }
}

// ================= GEMM engine B: 2-term, 3 tiles, 3-stage ring =========
constexpr int GSTAGE2 = 25600;
constexpr int GEMM2_SMEM = 3 * GSTAGE2;    // 76800

__device__ __forceinline__ void g2t_load(const __nv_bfloat16* Ah, const __nv_bfloat16* Al,
                                         const __nv_bfloat16* Bh,
                                         int lda, int ldb, uint32_t base, int koff, int t) {
    #pragma unroll
    for (int j = 0; j < 2; j++) {
        int g = j * 256 + t;
        int row = g >> 2, c16 = g & 3;
        cpa16(base +         row * 80 + c16 * 16, Ah + (size_t)row * lda + koff + c16 * 8);
        cpa16(base + 10240 + row * 80 + c16 * 16, Al + (size_t)row * lda + koff + c16 * 8);
    }
    {
        int row = t >> 2, c16 = t & 3;
        cpa16(base + 20480 + row * 80 + c16 * 16, Bh + (size_t)row * ldb + koff + c16 * 8);
    }
    asm volatile("cp.async.commit_group;");
}

__device__ __forceinline__ void gemm_main2t(const __nv_bfloat16* Ah, const __nv_bfloat16* Al,
                                            const __nv_bfloat16* Bh,
                                            int lda, int ldb, int nchunks,
                                            uint32_t su, float acc[2][4][4]) {
    const int t = threadIdx.x;
    const int lane = t & 31, wid = t >> 5;
    const int wm = wid & 3, wn = wid >> 2;

    g2t_load(Ah, Al, Bh, lda, ldb, su, 0, t);
    if (nchunks > 1) g2t_load(Ah, Al, Bh, lda, ldb, su + GSTAGE2, 32, t);
    int rb = 0;
    for (int i = 0; i < nchunks; i++) {
        if (i + 1 < nchunks) { asm volatile("cp.async.wait_group 1;" ::: "memory"); }
        else                 { asm volatile("cp.async.wait_group 0;" ::: "memory"); }
        __syncthreads();
        if (i + 2 < nchunks) {
            int wb = rb + 2; if (wb >= 3) wb -= 3;
            g2t_load(Ah, Al, Bh, lda, ldb, su + wb * GSTAGE2, (i + 2) * 32, t);
        }
        const uint32_t ab = su + rb * GSTAGE2;
        #pragma unroll
        for (int k16 = 0; k16 < 2; k16++) {
            uint32_t afh[2][4], afl[2][4];
            uint32_t a_addr = ab + (wm * 32 + (lane & 15)) * 80 + k16 * 32 + (lane >> 4) * 16;
            ldm4(a_addr,                 afh[0][0], afh[0][1], afh[0][2], afh[0][3]);
            ldm4(a_addr + 16 * 80,       afh[1][0], afh[1][1], afh[1][2], afh[1][3]);
            ldm4(a_addr + 10240,         afl[0][0], afl[0][1], afl[0][2], afl[0][3]);
            ldm4(a_addr + 10240 + 1280,  afl[1][0], afl[1][1], afl[1][2], afl[1][3]);
            uint32_t bfh[4][2];
            #pragma unroll
            for (int p = 0; p < 2; p++) {
                uint32_t b_addr = ab + 20480 + (wn * 32 + p * 16 + (lane & 15)) * 80
                                + k16 * 32 + ((lane >> 4) & 1) * 16;
                uint32_t r0, r1, r2, r3;
                ldm4(b_addr, r0, r1, r2, r3);
                bfh[2 * p][0] = r0; bfh[2 * p + 1][0] = r1;
                bfh[2 * p][1] = r2; bfh[2 * p + 1][1] = r3;
            }
            #pragma unroll
            for (int mi = 0; mi < 2; mi++)
                #pragma unroll
                for (int ni = 0; ni < 4; ni++) {
                    mma16816(acc[mi][ni], afh[mi], bfh[ni]);
                    mma16816(acc[mi][ni], afl[mi], bfh[ni]);
                }
        }
        if (++rb == 3) rb = 0;
    }
}

#define EPILOGUE_ITER(body)                                                    \
    {                                                                          \
        const int lane = threadIdx.x & 31, wid = threadIdx.x >> 5;             \
        const int wm = wid & 3, wn = wid >> 2;                                 \
        _Pragma("unroll")                                                      \
        for (int mi = 0; mi < 2; mi++)                                         \
            _Pragma("unroll")                                                  \
            for (int ni = 0; ni < 4; ni++)                                     \
                _Pragma("unroll")                                              \
                for (int e = 0; e < 4; e++) {                                  \
                    int row = wm * 32 + mi * 16 + (lane >> 2) + ((e >> 1) * 8);\
                    int col = wn * 32 + ni * 8 + (lane & 3) * 2 + (e & 1);     \
                    float v = acc[mi][ni][e];                                  \
                    body                                                       \
                }                                                              \
    }

// ================= projection kernels (one engine per kernel — no branch) ========
__global__ __launch_bounds__(256, 2) void k_qproj_t(const float* __restrict__ bq, int b0) {
    extern __shared__ __align__(128) uint8_t smem[];
    uint32_t su = smem_u32_of(smem);
    const int b = b0 + blockIdx.z, m0 = blockIdx.x * 128, n0 = blockIdx.y * 64;
    float acc[2][4][4] = {};
    gemm_main2t(g_xh + ((size_t)b * NP + m0) * CC, g_xl + ((size_t)b * NP + m0) * CC,
                g_wqh + (size_t)n0 * CC, CC, CC, 16, su, acc);
    EPILOGUE_ITER({
        v += bq[n0 + col];
        g_qh[((size_t)b * NP + m0 + row) * CC + n0 + col] = __float2bfloat16(v);
    })
}

// K projection: 2-term (K is bf16-rounded downstream anyway)
__global__ __launch_bounds__(256, 2) void k_kproj_t(const float* __restrict__ bkv) {
    extern __shared__ __align__(128) uint8_t smem[];
    uint32_t su = smem_u32_of(smem);
    const int b = blockIdx.z, m0 = blockIdx.x * 128, n0 = blockIdx.y * 64;
    float acc[2][4][4] = {};
    gemm_main2t(g_lh + ((size_t)b * MP + m0) * CC, g_ll + ((size_t)b * MP + m0) * CC,
                g_wkh + (size_t)n0 * CC, CC, CC, 16, su, acc);
    EPILOGUE_ITER({
        int o = n0 + col;
        int m = m0 + row;
        v += bkv[o];
        g_kh[(((size_t)b * NH + (o >> 6)) * MP + m) * HD + (o & 63)] = __float2bfloat16(v);
    })
}

// V projection: 3-term (direct output path), writes transposed split V
__global__ __launch_bounds__(256, 2) void k_vproj_t(const float* __restrict__ bkv) {
    extern __shared__ __align__(128) uint8_t smem[];
    uint32_t su = smem_u32_of(smem);
    const int b = blockIdx.z, m0 = blockIdx.x * 128, n0 = 512 + blockIdx.y * 64;
    float acc[2][4][4] = {};
    gemm_main3(g_lh + ((size_t)b * MP + m0) * CC, g_ll + ((size_t)b * MP + m0) * CC,
               g_wkh + (size_t)n0 * CC, g_wkl + (size_t)n0 * CC,
               CC, CC, 16, su, acc);
    EPILOGUE_ITER({
        int o2 = n0 + col - 512;
        int m = m0 + row;
        v += bkv[n0 + col];
        size_t idx = (((size_t)b * NH + (o2 >> 6)) * HD + (o2 & 63)) * MP + m;
        __nv_bfloat16 h = __float2bfloat16(v);
        g_vth[idx] = h;
        g_vtl[idx] = __float2bfloat16(v - __bfloat162float(h));
    })
}

// ================= fused flash attention =================
// smem: Qh[128][144] @0 (18432); chunk buf @18432 + buf*27648:
//   Kh 64x144 (9216), Vh +9216, Vl +18432.  total 73728.
constexpr int FPITCH  = 144;
constexpr int Q_BYTES = 128 * FPITCH;          // 18432
constexpr int T_BYTES = 64 * FPITCH;           // 9216
constexpr int CH_OFF  = Q_BYTES;               // 18432
constexpr int CH_SIZE = 3 * T_BYTES;           // 27648
constexpr int FLASH_SMEM = CH_OFF + 2 * CH_SIZE;   // 73728

__global__ __launch_bounds__(256, 2) void k_flash(float* __restrict__ out, int bh0) {
    extern __shared__ __align__(128) uint8_t fsm[];
    uint32_t su = smem_u32_of(fsm);
    const int bh = bh0 + blockIdx.y, b = bh >> 3, h = bh & 7;
    const int n0 = blockIdx.x * 128;
    const int t = threadIdx.x, lane = t & 31, w = t >> 5;

    const __nv_bfloat16* qhp = g_qh + ((size_t)b * NP + n0) * CC + h * HD;
    const __nv_bfloat16* khp = g_kh + (size_t)bh * MP * HD;
    const __nv_bfloat16* vhp = g_vth + (size_t)bh * HD * MP;
    const __nv_bfloat16* vlp = g_vtl + (size_t)bh * HD * MP;

    #pragma unroll
    for (int j = 0; j < 4; j++) {
        int g = j * 256 + t, row = g >> 3, c16 = g & 7;
        cpa16(su + row * FPITCH + c16 * 16, qhp + (size_t)row * CC + c16 * 8);
    }
    asm volatile("cp.async.commit_group;");

    auto load_chunk = [&](int ci, int buf) {
        uint32_t base = su + CH_OFF + buf * CH_SIZE;
        #pragma unroll
        for (int j = 0; j < 2; j++) {
            int g = j * 256 + t, row = g >> 3, c16 = g & 7;
            cpa16(base +               row * FPITCH + c16 * 16,
                  khp + (size_t)(ci * 64 + row) * HD + c16 * 8);
            cpa16(base + T_BYTES +     row * FPITCH + c16 * 16,
                  vhp + (size_t)row * MP + ci * 64 + c16 * 8);
            cpa16(base + 2 * T_BYTES + row * FPITCH + c16 * 16,
                  vlp + (size_t)row * MP + ci * 64 + c16 * 8);
        }
        asm volatile("cp.async.commit_group;");
    };
    load_chunk(0, 0);

    float l0 = 0.f, l1 = 0.f;
    float oa[8][4] = {};

    const uint32_t q_frag_base = su + (w * 16 + (lane & 15)) * FPITCH + (lane >> 4) * 16;
    const uint32_t kb_row = (lane & 15) * FPITCH + ((lane >> 4) & 1) * 16;

    for (int ci = 0; ci < 10; ci++) {
        const int buf = ci & 1;
        const uint32_t kb = su + CH_OFF + buf * CH_SIZE;

        asm volatile("cp.async.wait_group 0;" ::: "memory");
        __syncthreads();
        if (ci + 1 < 10) load_chunk(ci + 1, buf ^ 1);

        // ---- S = Qh * Kh  (1-term; Q and K bf16-rounded upstream) ----
        float sa[8][4] = {};
        #pragma unroll
        for (int g = 0; g < 4; g++) {
            uint32_t qfh[4];
            ldm4(q_frag_base + g * 32, qfh[0], qfh[1], qfh[2], qfh[3]);
            #pragma unroll
            for (int half = 0; half < 2; half++) {
                uint32_t bkh[4][2];
                #pragma unroll
                for (int p = 0; p < 2; p++) {
                    uint32_t addr = kb + (half * 32 + p * 16) * FPITCH + kb_row + g * 32;
                    uint32_t r0, r1, r2, r3;
                    ldm4(addr, r0, r1, r2, r3);
                    bkh[2 * p][0] = r0; bkh[2 * p + 1][0] = r1;
                    bkh[2 * p][1] = r2; bkh[2 * p + 1][1] = r3;
                }
                #pragma unroll
                for (int nb2 = 0; nb2 < 4; nb2++)
                    mma16816(sa[half * 4 + nb2], qfh, bkh[nb2]);
            }
        }

        // ---- fixed-shift softmax ----
        float ps0 = 0.f, ps1 = 0.f;
        if (ci == 9) {
            #pragma unroll
            for (int nb = 0; nb < 8; nb++)
                #pragma unroll
                for (int e = 0; e < 4; e++) {
                    int j = 576 + nb * 8 + (lane & 3) * 2 + (e & 1);
                    float ev = (j < MT) ? __expf(sa[nb][e] * ATT_SCALE) : 0.f;
                    sa[nb][e] = ev;
                    if (e < 2) ps0 += ev; else ps1 += ev;
                }
        } else {
            #pragma unroll
            for (int nb = 0; nb < 8; nb++)
                #pragma unroll
                for (int e = 0; e < 4; e++) {
                    float ev = __expf(sa[nb][e] * ATT_SCALE);
                    sa[nb][e] = ev;
                    if (e < 2) ps0 += ev; else ps1 += ev;
                }
        }
        ps0 += __shfl_xor_sync(0xffffffffu, ps0, 1);
        ps0 += __shfl_xor_sync(0xffffffffu, ps0, 2);
        ps1 += __shfl_xor_sync(0xffffffffu, ps1, 1);
        ps1 += __shfl_xor_sync(0xffffffffu, ps1, 2);
        l0 += ps0;
        l1 += ps1;

        // ---- PV: O += Ph*Vh + Ph*Vl + Pl*Vh  (3-term; direct output path) ----
        #pragma unroll
        for (int g = 0; g < 4; g++) {
            uint32_t aph[4], apl[4];
            #pragma unroll
            for (int q = 0; q < 2; q++) {
                int nb = 2 * g + q;
                float p0 = sa[nb][0], p1 = sa[nb][1], p2 = sa[nb][2], p3 = sa[nb][3];
                uint32_t hi01 = pack_bf2(p0, p1);
                uint32_t hi23 = pack_bf2(p2, p3);
                aph[2 * q]     = hi01;
                aph[2 * q + 1] = hi23;
                apl[2 * q]     = pack_bf2(p0 - b2f_lo(hi01), p1 - b2f_hi(hi01));
                apl[2 * q + 1] = pack_bf2(p2 - b2f_lo(hi23), p3 - b2f_hi(hi23));
            }
            #pragma unroll
            for (int half = 0; half < 2; half++) {
                uint32_t bvh[4][2], bvl[4][2];
                #pragma unroll
                for (int p = 0; p < 2; p++) {
                    uint32_t addr = kb + T_BYTES + (half * 32 + p * 16) * FPITCH
                                  + kb_row + g * 32;
                    uint32_t r0, r1, r2, r3;
                    ldm4(addr, r0, r1, r2, r3);
                    bvh[2 * p][0] = r0; bvh[2 * p + 1][0] = r1;
                    bvh[2 * p][1] = r2; bvh[2 * p + 1][1] = r3;
                    ldm4(addr + T_BYTES, r0, r1, r2, r3);
                    bvl[2 * p][0] = r0; bvl[2 * p + 1][0] = r1;
                    bvl[2 * p][1] = r2; bvl[2 * p + 1][1] = r3;
                }
                #pragma unroll
                for (int nd2 = 0; nd2 < 4; nd2++) {
                    int nd = half * 4 + nd2;
                    mma16816(oa[nd], aph, bvh[nd2]);
                    mma16816(oa[nd], aph, bvl[nd2]);
                    mma16816(oa[nd], apl, bvh[nd2]);
                }
            }
        }
    }

    const float inv0 = 1.f / l0, inv1 = 1.f / l1;
    const int r0 = w * 16 + (lane >> 2);
    const int nq0 = n0 + r0, nq1 = nq0 + 8;
    #pragma unroll
    for (int nd = 0; nd < 8; nd++) {
        int d = h * HD + nd * 8 + (lane & 3) * 2;
        if (nq0 < NT) {
            float2 v = make_float2(oa[nd][0] * inv0, oa[nd][1] * inv0);
            *(float2*)(out + ((size_t)b * NT + nq0) * CC + d) = v;
        }
        if (nq1 < NT) {
            float2 v = make_float2(oa[nd][2] * inv1, oa[nd][3] * inv1);
            *(float2*)(out + ((size_t)b * NT + nq1) * CC + d) = v;
        }
    }
}

// ================= support kernels =================
__global__ __launch_bounds__(256) void k_tsplit(const float* __restrict__ x) {
    __shared__ float tile[32][33];
    const int b = blockIdx.z, n0 = blockIdx.x * 32, c0 = blockIdx.y * 32;
    const int tx = threadIdx.x & 31, ty = threadIdx.x >> 5;
    const float* xp = x + ((size_t)b * CC + c0) * NT + n0;
    #pragma unroll
    for (int i = 0; i < 4; i++)
        tile[ty + 8 * i][tx] = xp[(size_t)(ty + 8 * i) * NT + tx];
    __syncthreads();
    #pragma unroll
    for (int i = 0; i < 4; i++) {
        int r = ty + 8 * i;
        float v = tile[tx][r];
        size_t o = ((size_t)b * NP + n0 + r) * CC + c0 + tx;
        __nv_bfloat16 h = __float2bfloat16(v);
        g_xh[o] = h;
        g_xl[o] = __float2bfloat16(v - __bfloat162float(h));
    }
}

__global__ void k_splitw(const float* __restrict__ Wq, const float* __restrict__ Wkv) {
    int i = blockIdx.x * 256 + threadIdx.x;
    if (i < CC * CC) {
        g_wqh[i] = __float2bfloat16(Wq[i]);
    }
    if (i < 2 * CC * CC) {
        float v = Wkv[i];
        __nv_bfloat16 h = __float2bfloat16(v);
        g_wkh[i] = h; g_wkl[i] = __float2bfloat16(v - __bfloat162float(h));
    }
}

// fused branches 1, 2, 3: one block per (b, c); pooled plane staged in SMEM
__global__ __launch_bounds__(224) void k_branch(const float* __restrict__ x,
        const float* __restrict__ w1a, const float* __restrict__ b1a,
        const float* __restrict__ w1b, const float* __restrict__ b1b,
        const float* __restrict__ w2, const float* __restrict__ b2,
        const float* __restrict__ w3, const float* __restrict__ b3) {
    __shared__ float pool_s[196];
    const int bc = blockIdx.x;
    const int b = bc / CC, c = bc % CC;
    const int t = threadIdx.x;

    if (t < 196) {
        int w4 = t % 14, h4 = t / 14;
        const float* xp = x + (((size_t)bc * HH) + 4 * h4) * WW + 4 * w4;
        float wa[4], wb_[4], wc[16];
        #pragma unroll
        for (int r = 0; r < 4; r++) { wa[r] = w1a[c * 4 + r]; wb_[r] = w1b[c * 4 + r]; }
        #pragma unroll
        for (int r = 0; r < 16; r++) wc[r] = w2[c * 16 + r];
        float ba = b1a[c];
        float l1 = b1b[c], l2 = b2[c], pool = 0.f;
        #pragma unroll
        for (int i = 0; i < 4; i++) {
            float4 xv = *(const float4*)(xp + (size_t)i * WW);
            float tmid = ba + xv.x * wa[0] + xv.y * wa[1] + xv.z * wa[2] + xv.w * wa[3];
            l1 += fmaxf(tmid, 0.f) * wb_[i];
            l2 += xv.x * wc[4 * i] + xv.y * wc[4 * i + 1] + xv.z * wc[4 * i + 2] + xv.w * wc[4 * i + 3];
            pool += xv.x + xv.y + xv.z + xv.w;
        }
        g_lf[((size_t)b * MT + t) * CC + c] = fmaxf(l1, 0.f);
        g_lf[((size_t)b * MT + 196 + t) * CC + c] = fmaxf(l2, 0.f);
        pool_s[t] = pool * (1.f / 16.f);
    }
    __syncthreads();
    if (t < 196) {
        int w4 = t % 14, h4 = t / 14;
        float s = b3[c];
        #pragma unroll
        for (int i = 0; i < 3; i++) {
            int hh = h4 - 1 + i;
            if (hh < 0 || hh >= 14) continue;
            #pragma unroll
            for (int j = 0; j < 3; j++) {
                int ww = w4 - 1 + j;
                if (ww < 0 || ww >= 14) continue;
                s += pool_s[hh * 14 + ww] * w3[c * 9 + i * 3 + j];
            }
        }
        g_lf[((size_t)b * MT + 392 + t) * CC + c] = fmaxf(s, 0.f);
    }
}

__global__ __launch_bounds__(128) void k_ln(const float* __restrict__ gamma,
                                            const float* __restrict__ beta) {
    const int row = blockIdx.x;
    const int b = row / MT, m = row - b * MT;
    const float* p = g_lf + (size_t)row * CC;
    const int t = threadIdx.x;
    float4 v = *(const float4*)(p + t * 4);
    float s = v.x + v.y + v.z + v.w;
    float ss = v.x * v.x + v.y * v.y + v.z * v.z + v.w * v.w;
    #pragma unroll
    for (int o = 16; o >= 1; o >>= 1) {
        s  += __shfl_xor_sync(0xffffffffu, s, o);
        ss += __shfl_xor_sync(0xffffffffu, ss, o);
    }
    __shared__ float sh[8];
    int w = t >> 5;
    if ((t & 31) == 0) { sh[w * 2] = s; sh[w * 2 + 1] = ss; }
    __syncthreads();
    s  = sh[0] + sh[2] + sh[4] + sh[6];
    ss = sh[1] + sh[3] + sh[5] + sh[7];
    float mu = s * (1.f / CC);
    float var = ss * (1.f / CC) - mu * mu;
    float r = rsqrtf(var + 1e-5f);
    float4 g = *(const float4*)(gamma + t * 4);
    float4 be = *(const float4*)(beta + t * 4);
    float o0 = (v.x - mu) * r * g.x + be.x;
    float o1 = (v.y - mu) * r * g.y + be.y;
    float o2 = (v.z - mu) * r * g.z + be.z;
    float o3 = (v.w - mu) * r * g.w + be.w;
    size_t base = ((size_t)b * MP + m) * CC + t * 4;
    __nv_bfloat16 h0 = __float2bfloat16(o0), h1 = __float2bfloat16(o1);
    __nv_bfloat16 h2 = __float2bfloat16(o2), h3 = __float2bfloat16(o3);
    g_lh[base + 0] = h0; g_ll[base + 0] = __float2bfloat16(o0 - __bfloat162float(h0));
    g_lh[base + 1] = h1; g_ll[base + 1] = __float2bfloat16(o1 - __bfloat162float(h1));
    g_lh[base + 2] = h2; g_ll[base + 2] = __float2bfloat16(o2 - __bfloat162float(h2));
    g_lh[base + 3] = h3; g_ll[base + 3] = __float2bfloat16(o3 - __bfloat162float(h3));
}

// ---------------- launch: pipelined schedule with tail-filling streams ----------------
extern "C" void kernel_launch(void* const* d_in, const int* in_sizes, int n_in,
                              void* d_out, int out_size) {
    const float* x     = (const float*)d_in[0];
    const float* Wq    = (const float*)d_in[1];
    const float* bq    = (const float*)d_in[2];
    const float* Wkv   = (const float*)d_in[3];
    const float* bkv   = (const float*)d_in[4];
    const float* w1a   = (const float*)d_in[5];
    const float* b1a   = (const float*)d_in[6];
    const float* w1b   = (const float*)d_in[7];
    const float* b1b   = (const float*)d_in[8];
    const float* w2    = (const float*)d_in[9];
    const float* b2    = (const float*)d_in[10];
    const float* w3    = (const float*)d_in[11];
    const float* b3    = (const float*)d_in[12];
    const float* gamma = (const float*)d_in[13];
    const float* beta  = (const float*)d_in[14];
    float* out = (float*)d_out;

    // one-time resource init (identical captured graph every call)
    static cudaStream_t s2 = nullptr, f0 = nullptr, f1 = nullptr;
    static cudaEvent_t e_fork = nullptr, e_kv = nullptr, e_d0 = nullptr, e_d1 = nullptr;
    static cudaEvent_t e_q[2] = {nullptr, nullptr};
    if (s2 == nullptr) {
        cudaStreamCreateWithFlags(&s2, cudaStreamNonBlocking);
        cudaStreamCreateWithFlags(&f0, cudaStreamNonBlocking);
        cudaStreamCreateWithFlags(&f1, cudaStreamNonBlocking);
        cudaEventCreateWithFlags(&e_fork, cudaEventDisableTiming);
        cudaEventCreateWithFlags(&e_kv,   cudaEventDisableTiming);
        cudaEventCreateWithFlags(&e_d0,   cudaEventDisableTiming);
        cudaEventCreateWithFlags(&e_d1,   cudaEventDisableTiming);
        for (int i = 0; i < 2; i++) cudaEventCreateWithFlags(&e_q[i], cudaEventDisableTiming);
        cudaFuncSetAttribute(k_flash,   cudaFuncAttributeMaxDynamicSharedMemorySize, FLASH_SMEM);
        cudaFuncSetAttribute(k_qproj_t, cudaFuncAttributeMaxDynamicSharedMemorySize, GEMM2_SMEM);
        cudaFuncSetAttribute(k_kproj_t, cudaFuncAttributeMaxDynamicSharedMemorySize, GEMM2_SMEM);
        cudaFuncSetAttribute(k_vproj_t, cudaFuncAttributeMaxDynamicSharedMemorySize, GEMM3_SMEM);
    }

    // main stream: weight split (needed by both chains), then fork
    k_splitw<<<(2 * CC * CC + 255) / 256, 256>>>(Wq, Wkv);
    cudaEventRecord(e_fork, 0);
    cudaStreamWaitEvent(s2, e_fork, 0);

    // side chain (s2): branches -> LN -> K proj (2-term) -> V proj (3-term) -> e_kv
    k_branch<<<BB * CC, 224, 0, s2>>>(x, w1a, b1a, w1b, b1b, w2, b2, w3, b3);
    k_ln<<<BB * MT, 128, 0, s2>>>(gamma, beta);
    k_kproj_t<<<dim3(MP / 128, 8, BB), 256, GEMM2_SMEM, s2>>>(bkv);
    k_vproj_t<<<dim3(MP / 128, 8, BB), 256, GEMM3_SMEM, s2>>>(bkv);
    cudaEventRecord(e_kv, s2);

    // main chain: x transpose/split, then 2 qproj halves (4 batches each)
    k_tsplit<<<dim3(NT / 32, CC / 32, BB), 256>>>(x);
    for (int half = 0; half < 2; half++) {
        k_qproj_t<<<dim3(NP / 128, CC / 64, 4), 256, GEMM2_SMEM>>>(bq, 4 * half);
        cudaEventRecord(e_q[half], 0);
    }

    // flash: 4 slices (2 batches each) alternating across two streams
    cudaStreamWaitEvent(f0, e_kv, 0);
    cudaStreamWaitEvent(f1, e_kv, 0);
    for (int sIdx = 0; sIdx < 4; sIdx++) {
        cudaStream_t fs = (sIdx & 1) ? f1 : f0;
        cudaStreamWaitEvent(fs, e_q[sIdx >> 1], 0);
        k_flash<<<dim3(NP / 128, 2 * NH), 256, FLASH_SMEM, fs>>>(out, 2 * sIdx * NH);
    }
    cudaEventRecord(e_d0, f0);
    cudaEventRecord(e_d1, f1);

    // join everything back into the capture stream
    cudaStreamWaitEvent(0, e_d0, 0);
    cudaStreamWaitEvent(0, e_d1, 0);
}